// round 7
// baseline (speedup 1.0000x reference)
#include <cuda_runtime.h>

#define NN 100000
#define EE 3200000
#define IND 128
#define OUTD 64

// Scratch (device globals — no allocation allowed)
__device__ float g_h[(size_t)NN * OUTD];    // 25.6 MB
__device__ float g_out[(size_t)NN * OUTD];  // 25.6 MB accumulation target (true global space)
__device__ float g_hs[NN];
__device__ float g_ht[NN];
__device__ float g_ex[EE];                  // 12.8 MB
__device__ float g_esum[NN];

// ---------------------------------------------------------------------------
// init: zero the accumulator scratch and e_sum
// ---------------------------------------------------------------------------
__global__ void init_kernel() {
    int i = blockIdx.x * blockDim.x + threadIdx.x;
    if (i < NN * OUTD) g_out[i] = 0.0f;
    if (i < NN) g_esum[i] = 0.0f;
}

// ---------------------------------------------------------------------------
// GEMM: h = x @ W  (N x 128) @ (128 x 64), fused hs = h.a_src, ht = h.a_tgt
// Block: 256 threads, tile 32 rows x 64 cols.
// Thread (cg = tid&15, rp = tid>>4): rows {b*32+rp, b*32+rp+16}, cols 4cg..4cg+3
// W staged in SMEM as float4 (32 KB). x read via float4 LDG.
// ---------------------------------------------------------------------------
__device__ __forceinline__ void fma4(float4& acc, float s, const float4 w) {
    acc.x += s * w.x; acc.y += s * w.y; acc.z += s * w.z; acc.w += s * w.w;
}

__global__ void gemm_kernel(const float* __restrict__ x,
                            const float* __restrict__ W,
                            const float* __restrict__ a_src,
                            const float* __restrict__ a_tgt) {
    __shared__ float4 sW[IND * 16];  // 32 KB: sW[k*16+cg] = W[k][4cg..4cg+3]
    int tid = threadIdx.x;
    const float4* W4 = (const float4*)W;
    for (int i = tid; i < IND * 16; i += 256) sW[i] = W4[i];
    __syncthreads();

    int cg = tid & 15;
    int rp = tid >> 4;
    int r0 = blockIdx.x * 32 + rp;   // NN = 100000 = 3125 * 32, exact fit
    int r1 = r0 + 16;

    const float4* x0 = (const float4*)(x + (size_t)r0 * IND);
    const float4* x1 = (const float4*)(x + (size_t)r1 * IND);

    float4 acc0 = {0.f, 0.f, 0.f, 0.f};
    float4 acc1 = {0.f, 0.f, 0.f, 0.f};

#pragma unroll
    for (int k4 = 0; k4 < IND / 4; k4++) {
        float4 a = __ldg(x0 + k4);
        float4 b = __ldg(x1 + k4);
        float4 w0 = sW[(4 * k4 + 0) * 16 + cg];
        fma4(acc0, a.x, w0); fma4(acc1, b.x, w0);
        float4 w1 = sW[(4 * k4 + 1) * 16 + cg];
        fma4(acc0, a.y, w1); fma4(acc1, b.y, w1);
        float4 w2 = sW[(4 * k4 + 2) * 16 + cg];
        fma4(acc0, a.z, w2); fma4(acc1, b.z, w2);
        float4 w3 = sW[(4 * k4 + 3) * 16 + cg];
        fma4(acc0, a.w, w3); fma4(acc1, b.w, w3);
    }

    float4* h4 = (float4*)g_h;
    h4[(size_t)r0 * 16 + cg] = acc0;
    h4[(size_t)r1 * 16 + cg] = acc1;

    // fused hs/ht: per-row dot with a_src / a_tgt, reduce over 16 lanes (same rp)
    float4 as = __ldg((const float4*)a_src + cg);
    float4 at = __ldg((const float4*)a_tgt + cg);
    float ps0 = acc0.x * as.x + acc0.y * as.y + acc0.z * as.z + acc0.w * as.w;
    float pt0 = acc0.x * at.x + acc0.y * at.y + acc0.z * at.z + acc0.w * at.w;
    float ps1 = acc1.x * as.x + acc1.y * as.y + acc1.z * as.z + acc1.w * as.w;
    float pt1 = acc1.x * at.x + acc1.y * at.y + acc1.z * at.z + acc1.w * at.w;

#pragma unroll
    for (int o = 8; o; o >>= 1) {
        ps0 += __shfl_down_sync(0xffffffffu, ps0, o, 16);
        pt0 += __shfl_down_sync(0xffffffffu, pt0, o, 16);
        ps1 += __shfl_down_sync(0xffffffffu, ps1, o, 16);
        pt1 += __shfl_down_sync(0xffffffffu, pt1, o, 16);
    }
    if (cg == 0) {
        g_hs[r0] = ps0; g_ht[r0] = pt0;
        g_hs[r1] = ps1; g_ht[r1] = pt1;
    }
}

// ---------------------------------------------------------------------------
// Edge pass 1: e_exp = exp(leaky_relu(hs[src]+ht[tgt]) * w); accumulate e_sum.
// edge_index is INT32 (JAX x64 disabled downcasts int64 -> int32).
// Softmax max-shift omitted: logits bounded (|e| ~< 10), ratios identical.
// ---------------------------------------------------------------------------
__global__ void edge1_kernel(const int* __restrict__ ei,
                             const float* __restrict__ ew) {
    int i = blockIdx.x * 256 + threadIdx.x;
    if (i >= EE) return;
    int s = __ldg(ei + i);
    int t = __ldg(ei + EE + i);
    float e = g_hs[s] + g_ht[t];
    e = e > 0.f ? e : 0.2f * e;          // leaky_relu(0.2)
    e *= __ldg(ew + i);
    float v = __expf(e);
    g_ex[i] = v;
    atomicAdd(&g_esum[t], v);
}

// ---------------------------------------------------------------------------
// Edge pass 2: g_out[tgt] += alpha * h[src].  8 threads/edge, each does 8
// floats via two red.global.add.v4.f32 into DEVICE-GLOBAL scratch.
// ---------------------------------------------------------------------------
__global__ void edge2_kernel(const int* __restrict__ ei) {
    unsigned gid = blockIdx.x * 256u + threadIdx.x;
    int i = gid >> 3;   // edge id
    int c = gid & 7;    // 8-float chunk within the 64-wide row
    if (i >= EE) return;

    int s = __ldg(ei + i);
    int t = __ldg(ei + EE + i);
    float alpha = g_ex[i] / (g_esum[t] + 1e-10f);

    const float4* hp = (const float4*)(g_h + (size_t)s * OUTD) + c * 2;
    float4 h0 = hp[0];
    float4 h1 = hp[1];

    float* op = g_out + (size_t)t * OUTD + c * 8;
    asm volatile("red.global.add.v4.f32 [%0], {%1,%2,%3,%4};"
                 :: "l"(op),
                    "f"(alpha * h0.x), "f"(alpha * h0.y),
                    "f"(alpha * h0.z), "f"(alpha * h0.w)
                 : "memory");
    asm volatile("red.global.add.v4.f32 [%0], {%1,%2,%3,%4};"
                 :: "l"(op + 4),
                    "f"(alpha * h1.x), "f"(alpha * h1.y),
                    "f"(alpha * h1.z), "f"(alpha * h1.w)
                 : "memory");
}

// ---------------------------------------------------------------------------
// finalize: copy scratch accumulator to harness output buffer (plain stores —
// safe on any address space)
// ---------------------------------------------------------------------------
__global__ void finalize_kernel(float* __restrict__ out) {
    int i = blockIdx.x * 256 + threadIdx.x;
    if (i < NN * OUTD / 4) {
        ((float4*)out)[i] = ((const float4*)g_out)[i];
    }
}

// ---------------------------------------------------------------------------
extern "C" void kernel_launch(void* const* d_in, const int* in_sizes, int n_in,
                              void* d_out, int out_size) {
    const float* x     = (const float*)d_in[0];
    const int*   ei    = (const int*)d_in[1];
    const float* ew    = (const float*)d_in[2];
    const float* W     = (const float*)d_in[3];
    const float* a_src = (const float*)d_in[4];
    const float* a_tgt = (const float*)d_in[5];
    float*       out   = (float*)d_out;

    init_kernel<<<(NN * OUTD + 255) / 256, 256>>>();
    gemm_kernel<<<NN / 32, 256>>>(x, W, a_src, a_tgt);
    edge1_kernel<<<(EE + 255) / 256, 256>>>(ei, ew);
    edge2_kernel<<<(unsigned)((size_t)EE * 8 / 256), 256>>>(ei);
    finalize_kernel<<<(NN * OUTD / 4 + 255) / 256, 256>>>(out);
}

// round 8
// speedup vs baseline: 1.4846x; 1.4846x over previous
#include <cuda_runtime.h>

#define NN 100000
#define EE 3200000
#define IND 128
#define OUTD 64

#define SCAN_BLK 512
#define SCAN_NBLK ((NN + SCAN_BLK - 1) / SCAN_BLK)   // 196

// Scratch (device globals — no allocation allowed)
__device__ float g_h[(size_t)NN * OUTD];    // 25.6 MB
__device__ float g_hs[NN];
__device__ float g_ht[NN];
__device__ int   g_cnt[NN];                 // in-degree
__device__ int   g_base[NN];                // CSR row start (exclusive scan)
__device__ int   g_pos[NN];                 // scatter cursor (copy of base)
__device__ int   g_bsum[SCAN_NBLK];         // per-block scan partials
__device__ int2  g_bin[EE];                 // packed (src, e_exp bits), 25.6 MB

// ---------------------------------------------------------------------------
// init: zero the degree counters
// ---------------------------------------------------------------------------
__global__ void init_kernel() {
    int i = blockIdx.x * blockDim.x + threadIdx.x;
    if (i < NN) g_cnt[i] = 0;
}

// ---------------------------------------------------------------------------
// GEMM: h = x @ W  (N x 128) @ (128 x 64), fused hs = h.a_src, ht = h.a_tgt
// ---------------------------------------------------------------------------
__device__ __forceinline__ void fma4(float4& acc, float s, const float4 w) {
    acc.x += s * w.x; acc.y += s * w.y; acc.z += s * w.z; acc.w += s * w.w;
}

__global__ void gemm_kernel(const float* __restrict__ x,
                            const float* __restrict__ W,
                            const float* __restrict__ a_src,
                            const float* __restrict__ a_tgt) {
    __shared__ float4 sW[IND * 16];  // 32 KB: sW[k*16+cg] = W[k][4cg..4cg+3]
    int tid = threadIdx.x;
    const float4* W4 = (const float4*)W;
    for (int i = tid; i < IND * 16; i += 256) sW[i] = W4[i];
    __syncthreads();

    int cg = tid & 15;
    int rp = tid >> 4;
    int r0 = blockIdx.x * 32 + rp;   // NN = 3125 * 32, exact
    int r1 = r0 + 16;

    const float4* x0 = (const float4*)(x + (size_t)r0 * IND);
    const float4* x1 = (const float4*)(x + (size_t)r1 * IND);

    float4 acc0 = {0.f, 0.f, 0.f, 0.f};
    float4 acc1 = {0.f, 0.f, 0.f, 0.f};

#pragma unroll
    for (int k4 = 0; k4 < IND / 4; k4++) {
        float4 a = __ldg(x0 + k4);
        float4 b = __ldg(x1 + k4);
        float4 w0 = sW[(4 * k4 + 0) * 16 + cg];
        fma4(acc0, a.x, w0); fma4(acc1, b.x, w0);
        float4 w1 = sW[(4 * k4 + 1) * 16 + cg];
        fma4(acc0, a.y, w1); fma4(acc1, b.y, w1);
        float4 w2 = sW[(4 * k4 + 2) * 16 + cg];
        fma4(acc0, a.z, w2); fma4(acc1, b.z, w2);
        float4 w3 = sW[(4 * k4 + 3) * 16 + cg];
        fma4(acc0, a.w, w3); fma4(acc1, b.w, w3);
    }

    float4* h4 = (float4*)g_h;
    h4[(size_t)r0 * 16 + cg] = acc0;
    h4[(size_t)r1 * 16 + cg] = acc1;

    float4 as = __ldg((const float4*)a_src + cg);
    float4 at = __ldg((const float4*)a_tgt + cg);
    float ps0 = acc0.x * as.x + acc0.y * as.y + acc0.z * as.z + acc0.w * as.w;
    float pt0 = acc0.x * at.x + acc0.y * at.y + acc0.z * at.z + acc0.w * at.w;
    float ps1 = acc1.x * as.x + acc1.y * as.y + acc1.z * as.z + acc1.w * as.w;
    float pt1 = acc1.x * at.x + acc1.y * at.y + acc1.z * at.z + acc1.w * at.w;

#pragma unroll
    for (int o = 8; o; o >>= 1) {
        ps0 += __shfl_down_sync(0xffffffffu, ps0, o, 16);
        pt0 += __shfl_down_sync(0xffffffffu, pt0, o, 16);
        ps1 += __shfl_down_sync(0xffffffffu, ps1, o, 16);
        pt1 += __shfl_down_sync(0xffffffffu, pt1, o, 16);
    }
    if (cg == 0) {
        g_hs[r0] = ps0; g_ht[r0] = pt0;
        g_hs[r1] = ps1; g_ht[r1] = pt1;
    }
}

// ---------------------------------------------------------------------------
// Histogram of target nodes
// ---------------------------------------------------------------------------
__global__ void hist_kernel(const int* __restrict__ ei) {
    int i = blockIdx.x * 256 + threadIdx.x;
    if (i >= EE) return;
    atomicAdd(&g_cnt[__ldg(ei + EE + i)], 1);
}

// ---------------------------------------------------------------------------
// 3-step exclusive prefix scan of g_cnt -> g_base
// ---------------------------------------------------------------------------
__global__ void scan_a_kernel() {
    __shared__ int s[SCAN_BLK];
    int tid = threadIdx.x;
    int i = blockIdx.x * SCAN_BLK + tid;
    int v = (i < NN) ? g_cnt[i] : 0;
    s[tid] = v;
    __syncthreads();
#pragma unroll
    for (int off = 1; off < SCAN_BLK; off <<= 1) {
        int t = (tid >= off) ? s[tid - off] : 0;
        __syncthreads();
        s[tid] += t;
        __syncthreads();
    }
    if (i < NN) g_base[i] = s[tid] - v;            // exclusive within block
    if (tid == SCAN_BLK - 1) g_bsum[blockIdx.x] = s[tid];
}

__global__ void scan_b_kernel() {
    __shared__ int s[256];
    int tid = threadIdx.x;
    int v = (tid < SCAN_NBLK) ? g_bsum[tid] : 0;
    s[tid] = v;
    __syncthreads();
#pragma unroll
    for (int off = 1; off < 256; off <<= 1) {
        int t = (tid >= off) ? s[tid - off] : 0;
        __syncthreads();
        s[tid] += t;
        __syncthreads();
    }
    if (tid < SCAN_NBLK) g_bsum[tid] = s[tid] - v; // exclusive
}

__global__ void scan_c_kernel() {
    int i = blockIdx.x * SCAN_BLK + threadIdx.x;
    if (i >= NN) return;
    int b = g_base[i] + g_bsum[blockIdx.x];
    g_base[i] = b;
    g_pos[i] = b;
}

// ---------------------------------------------------------------------------
// Scatter: per edge compute e_exp and bin (src, e_exp) under its target.
// Softmax max-shift omitted: logits bounded (|e| small), ratios identical.
// ---------------------------------------------------------------------------
__global__ void scatter_kernel(const int* __restrict__ ei,
                               const float* __restrict__ ew) {
    int i = blockIdx.x * 256 + threadIdx.x;
    if (i >= EE) return;
    int s = __ldg(ei + i);
    int t = __ldg(ei + EE + i);
    float e = g_hs[s] + g_ht[t];
    e = e > 0.f ? e : 0.2f * e;          // leaky_relu(0.2)
    e *= __ldg(ew + i);
    float v = __expf(e);
    int p = atomicAdd(&g_pos[t], 1);
    g_bin[p] = make_int2(s, __float_as_int(v));
}

// ---------------------------------------------------------------------------
// Aggregate: one warp per target node. Coalesced bin read, warp-coalesced
// 256B gather of h[src] (L2-hit), fused softmax normalization, single store
// straight to d_out. No atomics, no separate e_sum pass, no init/finalize.
// ---------------------------------------------------------------------------
__global__ void agg_kernel(float* __restrict__ out) {
    int w = (blockIdx.x * 256 + threadIdx.x) >> 5;   // node id
    int lane = threadIdx.x & 31;
    if (w >= NN) return;

    int base = g_base[w];
    int deg  = g_cnt[w];

    const float2* h2 = (const float2*)g_h;
    float2 acc = {0.f, 0.f};
    float  vsum = 0.f;

    for (int e0 = 0; e0 < deg; e0 += 32) {
        int nn = deg - e0;
        if (nn > 32) nn = 32;
        int2 be = make_int2(0, 0);
        if (lane < nn) be = g_bin[base + e0 + lane];
        float v = __int_as_float(be.y);
        if (lane < nn) vsum += v;

        for (int j = 0; j < nn; j++) {
            int   s  = __shfl_sync(0xffffffffu, be.x, j);
            float vv = __shfl_sync(0xffffffffu, v, j);
            float2 hv = h2[(size_t)s * 32 + lane];
            acc.x += vv * hv.x;
            acc.y += vv * hv.y;
        }
    }

#pragma unroll
    for (int o = 16; o; o >>= 1) vsum += __shfl_xor_sync(0xffffffffu, vsum, o);

    float inv = 1.f / (vsum + 1e-10f);
    ((float2*)out)[(size_t)w * 32 + lane] = make_float2(acc.x * inv, acc.y * inv);
}

// ---------------------------------------------------------------------------
extern "C" void kernel_launch(void* const* d_in, const int* in_sizes, int n_in,
                              void* d_out, int out_size) {
    const float* x     = (const float*)d_in[0];
    const int*   ei    = (const int*)d_in[1];
    const float* ew    = (const float*)d_in[2];
    const float* W     = (const float*)d_in[3];
    const float* a_src = (const float*)d_in[4];
    const float* a_tgt = (const float*)d_in[5];
    float*       out   = (float*)d_out;

    init_kernel<<<(NN + 255) / 256, 256>>>();
    gemm_kernel<<<NN / 32, 256>>>(x, W, a_src, a_tgt);
    hist_kernel<<<(EE + 255) / 256, 256>>>(ei);
    scan_a_kernel<<<SCAN_NBLK, SCAN_BLK>>>();
    scan_b_kernel<<<1, 256>>>();
    scan_c_kernel<<<SCAN_NBLK, SCAN_BLK>>>();
    scatter_kernel<<<(EE + 255) / 256, 256>>>(ei, ew);
    agg_kernel<<<(NN * 32 + 255) / 256, 256>>>(out);
}

// round 10
// speedup vs baseline: 1.8767x; 1.2641x over previous
#include <cuda_runtime.h>
#include <cuda_bf16.h>
#include <cstdint>

#define NN 100000
#define EE 3200000
#define IND 128
#define OUTD 64

#define SCAN_BLK 512
#define SCAN_NBLK ((NN + SCAN_BLK - 1) / SCAN_BLK)   // 196
#define NTILE ((NN + 127) / 128)                     // 782

// Scratch (device globals — no allocation allowed)
__device__ float g_h[(size_t)NN * OUTD];    // 25.6 MB
__device__ float g_hs[NN];
__device__ float g_ht[NN];
__device__ int   g_cnt[NN];                 // in-degree
__device__ int   g_base[NN];                // CSR row start
__device__ int   g_pos[NN];                 // scatter cursor
__device__ int   g_bsum[SCAN_NBLK];
__device__ int2  g_bin[EE];                 // packed (src, e_exp bits), 25.6 MB
__device__ uint2 g_Bfh[2048];               // W bf16-hi mma fragments (16 KB)
__device__ uint2 g_Bfl[2048];               // W bf16-lo mma fragments (16 KB)

// ---------------------------------------------------------------------------
// helpers
// ---------------------------------------------------------------------------
__device__ __forceinline__ uint32_t pack_bf16x2(float lo, float hi) {
    uint32_t r;
    asm("cvt.rn.bf16x2.f32 %0, %1, %2;" : "=r"(r) : "f"(hi), "f"(lo));
    return r;
}
__device__ __forceinline__ float2 bf16_resid(float2 p) {
    float rx = p.x - __bfloat162float(__float2bfloat16(p.x));
    float ry = p.y - __bfloat162float(__float2bfloat16(p.y));
    return make_float2(rx, ry);
}
__device__ __forceinline__ void mma16816(float* c,
                                         uint32_t a0, uint32_t a1, uint32_t a2, uint32_t a3,
                                         uint32_t b0, uint32_t b1) {
    asm volatile(
        "mma.sync.aligned.m16n8k16.row.col.f32.bf16.bf16.f32 "
        "{%0,%1,%2,%3}, {%4,%5,%6,%7}, {%8,%9}, {%0,%1,%2,%3};"
        : "+f"(c[0]), "+f"(c[1]), "+f"(c[2]), "+f"(c[3])
        : "r"(a0), "r"(a1), "r"(a2), "r"(a3), "r"(b0), "r"(b1));
}

// ---------------------------------------------------------------------------
// init: zero the degree counters
// ---------------------------------------------------------------------------
__global__ void init_kernel() {
    int i = blockIdx.x * blockDim.x + threadIdx.x;
    if (i < NN) g_cnt[i] = 0;
}

// ---------------------------------------------------------------------------
// W setup: build per-lane mma B fragments (col-major k16n8), bf16 hi + lo.
// Entry e = ks*256 + nt*32 + lane. b0 = W[k0+2tig..+1][n], b1 = W[k0+8+2tig..+1][n]
// ---------------------------------------------------------------------------
__global__ void wsetup_kernel(const float* __restrict__ W) {
    for (int e = threadIdx.x; e < 2048; e += 256) {
        int lane = e & 31;
        int nt = (e >> 5) & 7;
        int ks = e >> 8;
        int gid = lane >> 2, tig = lane & 3;
        int n = nt * 8 + gid;
        int k0 = ks * 16 + 2 * tig;
        float w00 = __ldg(W + (k0 + 0) * OUTD + n);
        float w01 = __ldg(W + (k0 + 1) * OUTD + n);
        float w10 = __ldg(W + (k0 + 8) * OUTD + n);
        float w11 = __ldg(W + (k0 + 9) * OUTD + n);
        uint2 bh, bl;
        bh.x = pack_bf16x2(w00, w01);
        bh.y = pack_bf16x2(w10, w11);
        float2 r0 = bf16_resid(make_float2(w00, w01));
        float2 r1 = bf16_resid(make_float2(w10, w11));
        bl.x = pack_bf16x2(r0.x, r0.y);
        bl.y = pack_bf16x2(r1.x, r1.y);
        g_Bfh[e] = bh;
        g_Bfl[e] = bl;
    }
}

// ---------------------------------------------------------------------------
// GEMM via mma.sync (HMMA bf16, fp32 acc), bf16x3 split for fp32 accuracy.
// CTA = 256 threads (8 warps x 16 rows) = 128-row tile, full K=128, N=64.
// A fragments loaded straight from global (sector-aligned LDG.64), B fragments
// from SMEM (conflict-free LDS.64). Epilogue stores h + fused hs/ht dots.
// ---------------------------------------------------------------------------
__global__ void __launch_bounds__(256)
gemm_mma_kernel(const float* __restrict__ x,
                const float* __restrict__ a_src,
                const float* __restrict__ a_tgt) {
    __shared__ uint2 sBh[2048];
    __shared__ uint2 sBl[2048];
    __shared__ float sAs[64];
    __shared__ float sAt[64];

    int tid = threadIdx.x;
    for (int i = tid; i < 2048; i += 256) { sBh[i] = g_Bfh[i]; sBl[i] = g_Bfl[i]; }
    if (tid < 64) { sAs[tid] = __ldg(a_src + tid); sAt[tid] = __ldg(a_tgt + tid); }
    __syncthreads();

    int wid = tid >> 5, lane = tid & 31;
    int gid = lane >> 2, tig = lane & 3;
    int r0 = blockIdx.x * 128 + wid * 16 + gid;
    int r1 = r0 + 8;
    bool v0 = r0 < NN, v1 = r1 < NN;
    const float2* x0 = (const float2*)x + (size_t)r0 * 64;
    const float2* x1 = (const float2*)x + (size_t)r1 * 64;

    float acc[8][4];
#pragma unroll
    for (int nt = 0; nt < 8; nt++)
        acc[nt][0] = acc[nt][1] = acc[nt][2] = acc[nt][3] = 0.f;

#pragma unroll
    for (int ks = 0; ks < 8; ks++) {
        float2 z = make_float2(0.f, 0.f);
        // a0: (row gid, cols k0+2tig..+1); a1: row+8; a2: cols +8; a3: both
        float2 p0 = v0 ? __ldg(x0 + ks * 8 + tig)     : z;
        float2 p1 = v1 ? __ldg(x1 + ks * 8 + tig)     : z;
        float2 p2 = v0 ? __ldg(x0 + ks * 8 + 4 + tig) : z;
        float2 p3 = v1 ? __ldg(x1 + ks * 8 + 4 + tig) : z;

        uint32_t ah0 = pack_bf16x2(p0.x, p0.y);
        uint32_t ah1 = pack_bf16x2(p1.x, p1.y);
        uint32_t ah2 = pack_bf16x2(p2.x, p2.y);
        uint32_t ah3 = pack_bf16x2(p3.x, p3.y);
        float2 q0 = bf16_resid(p0), q1 = bf16_resid(p1);
        float2 q2 = bf16_resid(p2), q3 = bf16_resid(p3);
        uint32_t al0 = pack_bf16x2(q0.x, q0.y);
        uint32_t al1 = pack_bf16x2(q1.x, q1.y);
        uint32_t al2 = pack_bf16x2(q2.x, q2.y);
        uint32_t al3 = pack_bf16x2(q3.x, q3.y);

#pragma unroll
        for (int nt = 0; nt < 8; nt++) {
            uint2 bh = sBh[ks * 256 + nt * 32 + lane];
            uint2 bl = sBl[ks * 256 + nt * 32 + lane];
            mma16816(acc[nt], ah0, ah1, ah2, ah3, bh.x, bh.y);  // hi*hi
            mma16816(acc[nt], ah0, ah1, ah2, ah3, bl.x, bl.y);  // hi*lo
            mma16816(acc[nt], al0, al1, al2, al3, bh.x, bh.y);  // lo*hi
        }
    }

    // Epilogue: c0/c1 -> (row gid, cols nt*8+2tig,+1); c2/c3 -> row+8
    float hs0 = 0.f, ht0 = 0.f, hs1 = 0.f, ht1 = 0.f;
    float2* h2 = (float2*)g_h;
#pragma unroll
    for (int nt = 0; nt < 8; nt++) {
        int cp = nt * 4 + tig;                    // float2 column index
        if (v0) h2[(size_t)r0 * 32 + cp] = make_float2(acc[nt][0], acc[nt][1]);
        if (v1) h2[(size_t)r1 * 32 + cp] = make_float2(acc[nt][2], acc[nt][3]);
        float as0 = sAs[2 * cp], as1 = sAs[2 * cp + 1];
        float at0 = sAt[2 * cp], at1 = sAt[2 * cp + 1];
        hs0 += acc[nt][0] * as0 + acc[nt][1] * as1;
        ht0 += acc[nt][0] * at0 + acc[nt][1] * at1;
        hs1 += acc[nt][2] * as0 + acc[nt][3] * as1;
        ht1 += acc[nt][2] * at0 + acc[nt][3] * at1;
    }
#pragma unroll
    for (int o = 1; o <= 2; o <<= 1) {
        hs0 += __shfl_xor_sync(0xffffffffu, hs0, o);
        ht0 += __shfl_xor_sync(0xffffffffu, ht0, o);
        hs1 += __shfl_xor_sync(0xffffffffu, hs1, o);
        ht1 += __shfl_xor_sync(0xffffffffu, ht1, o);
    }
    if (tig == 0) {
        if (v0) { g_hs[r0] = hs0; g_ht[r0] = ht0; }
        if (v1) { g_hs[r1] = hs1; g_ht[r1] = ht1; }
    }
}

// ---------------------------------------------------------------------------
// Histogram of target nodes
// ---------------------------------------------------------------------------
__global__ void hist_kernel(const int* __restrict__ ei) {
    int i = blockIdx.x * 256 + threadIdx.x;
    if (i >= EE) return;
    atomicAdd(&g_cnt[__ldg(ei + EE + i)], 1);
}

// ---------------------------------------------------------------------------
// 3-step exclusive prefix scan of g_cnt -> g_base
// ---------------------------------------------------------------------------
__global__ void scan_a_kernel() {
    __shared__ int s[SCAN_BLK];
    int tid = threadIdx.x;
    int i = blockIdx.x * SCAN_BLK + tid;
    int v = (i < NN) ? g_cnt[i] : 0;
    s[tid] = v;
    __syncthreads();
#pragma unroll
    for (int off = 1; off < SCAN_BLK; off <<= 1) {
        int t = (tid >= off) ? s[tid - off] : 0;
        __syncthreads();
        s[tid] += t;
        __syncthreads();
    }
    if (i < NN) g_base[i] = s[tid] - v;
    if (tid == SCAN_BLK - 1) g_bsum[blockIdx.x] = s[tid];
}

__global__ void scan_b_kernel() {
    __shared__ int s[256];
    int tid = threadIdx.x;
    int v = (tid < SCAN_NBLK) ? g_bsum[tid] : 0;
    s[tid] = v;
    __syncthreads();
#pragma unroll
    for (int off = 1; off < 256; off <<= 1) {
        int t = (tid >= off) ? s[tid - off] : 0;
        __syncthreads();
        s[tid] += t;
        __syncthreads();
    }
    if (tid < SCAN_NBLK) g_bsum[tid] = s[tid] - v;
}

__global__ void scan_c_kernel() {
    int i = blockIdx.x * SCAN_BLK + threadIdx.x;
    if (i >= NN) return;
    int b = g_base[i] + g_bsum[blockIdx.x];
    g_base[i] = b;
    g_pos[i] = b;
}

// ---------------------------------------------------------------------------
// Scatter: per edge compute e_exp and bin (src, e_exp) under its target.
// Softmax max-shift omitted: logits bounded, ratios identical.
// ---------------------------------------------------------------------------
__global__ void scatter_kernel(const int* __restrict__ ei,
                               const float* __restrict__ ew) {
    int i = blockIdx.x * 256 + threadIdx.x;
    if (i >= EE) return;
    int s = __ldg(ei + i);
    int t = __ldg(ei + EE + i);
    float e = g_hs[s] + g_ht[t];
    e = e > 0.f ? e : 0.2f * e;          // leaky_relu(0.2)
    e *= __ldg(ew + i);
    float v = __expf(e);
    int p = atomicAdd(&g_pos[t], 1);
    g_bin[p] = make_int2(s, __float_as_int(v));
}

// ---------------------------------------------------------------------------
// Aggregate: one warp per target node; fused softmax normalization; direct
// store to d_out.
// ---------------------------------------------------------------------------
__global__ void agg_kernel(float* __restrict__ out) {
    int w = (blockIdx.x * 256 + threadIdx.x) >> 5;
    int lane = threadIdx.x & 31;
    if (w >= NN) return;

    int base = g_base[w];
    int deg  = g_cnt[w];

    const float2* h2 = (const float2*)g_h;
    float2 acc = {0.f, 0.f};
    float  vsum = 0.f;

    for (int e0 = 0; e0 < deg; e0 += 32) {
        int nn = deg - e0;
        if (nn > 32) nn = 32;
        int2 be = make_int2(0, 0);
        if (lane < nn) be = g_bin[base + e0 + lane];
        float v = __int_as_float(be.y);
        if (lane < nn) vsum += v;

        for (int j = 0; j < nn; j++) {
            int   s  = __shfl_sync(0xffffffffu, be.x, j);
            float vv = __shfl_sync(0xffffffffu, v, j);
            float2 hv = h2[(size_t)s * 32 + lane];
            acc.x += vv * hv.x;
            acc.y += vv * hv.y;
        }
    }

#pragma unroll
    for (int o = 16; o; o >>= 1) vsum += __shfl_xor_sync(0xffffffffu, vsum, o);

    float inv = 1.f / (vsum + 1e-10f);
    ((float2*)out)[(size_t)w * 32 + lane] = make_float2(acc.x * inv, acc.y * inv);
}

// ---------------------------------------------------------------------------
extern "C" void kernel_launch(void* const* d_in, const int* in_sizes, int n_in,
                              void* d_out, int out_size) {
    const float* x     = (const float*)d_in[0];
    const int*   ei    = (const int*)d_in[1];
    const float* ew    = (const float*)d_in[2];
    const float* W     = (const float*)d_in[3];
    const float* a_src = (const float*)d_in[4];
    const float* a_tgt = (const float*)d_in[5];
    float*       out   = (float*)d_out;

    init_kernel<<<(NN + 255) / 256, 256>>>();
    wsetup_kernel<<<1, 256>>>(W);
    gemm_mma_kernel<<<NTILE, 256>>>(x, a_src, a_tgt);
    hist_kernel<<<(EE + 255) / 256, 256>>>(ei);
    scan_a_kernel<<<SCAN_NBLK, SCAN_BLK>>>();
    scan_b_kernel<<<1, 256>>>();
    scan_c_kernel<<<SCAN_NBLK, SCAN_BLK>>>();
    scatter_kernel<<<(EE + 255) / 256, 256>>>(ei, ew);
    agg_kernel<<<(NN * 32 + 255) / 256, 256>>>(out);
}